// round 15
// baseline (speedup 1.0000x reference)
#include <cuda_runtime.h>
#include <cstdint>

#define NN 8
#define TT 64
#define VV 200
#define FF 64
#define FOUT 64
#define NT 512
#define KC 16          // u per chunk in kernelBtc
#define NCH 13         // chunks: 12 full (16u) + 1 partial (8u)

typedef unsigned long long u64;
typedef unsigned int u32;

__device__ __forceinline__ void cpa16(u32 dst, const void* src) {
    asm volatile("cp.async.cg.shared.global [%0], [%1], 16;" :: "r"(dst), "l"(src));
}
#define CP_COMMIT()   asm volatile("cp.async.commit_group;" ::: "memory")
#define CP_WAIT_ALL() asm volatile("cp.async.wait_group 0;" ::: "memory")
#define CP_WAIT_1()   asm volatile("cp.async.wait_group 1;" ::: "memory")

// pack two f32 -> bf16x2 (first arg -> LOW half, second -> HIGH half)
__device__ __forceinline__ u32 cvt_bf2(float lo, float hi) {
    u32 r; asm("cvt.rn.bf16x2.f32 %0, %1, %2;" : "=r"(r) : "f"(hi), "f"(lo)); return r;
}

// BF16 mma m16n8k16: D += A*B (fp32 accum, in place)
__device__ __forceinline__ void mma16(float* d, const u32* a, const u32* b) {
    asm volatile(
        "mma.sync.aligned.m16n8k16.row.col.f32.bf16.bf16.f32 "
        "{%0,%1,%2,%3},{%4,%5,%6,%7},{%8,%9},{%0,%1,%2,%3};"
        : "+f"(d[0]), "+f"(d[1]), "+f"(d[2]), "+f"(d[3])
        : "r"(a[0]), "r"(a[1]), "r"(a[2]), "r"(a[3]),
          "r"(b[0]), "r"(b[1]));
}

// scratch (static device globals; no runtime allocation)
__device__ __align__(16) float g_y0[(size_t)NT*VV*FOUT];
__device__ __align__(16) float g_y1[(size_t)NT*VV*FOUT];
__device__ __align__(16) float g_y2[(size_t)NT*VV*FOUT];
__device__ __align__(16) u32   g_y1p[(size_t)NT*100*FOUT];  // bf16x2 (u,u+1) pairs
__device__ __align__(16) u32   g_y2p[(size_t)NT*100*FOUT];

// ---------------------------------------------------------------------------
// kernelGtc: y_k = x @ Theta_k via bf16 mma, 3-term hi/lo split (~1e-5 acc).
// Packed-Theta stride 76 -> conflict-free LDS.64 B-fragment loads.
// ---------------------------------------------------------------------------
#define GQ 76    // uint2 row stride for packed Theta (conflict-free)

__global__ void __launch_bounds__(416) kernelGtc(
        const float* __restrict__ x,
        const float* __restrict__ Theta) {
    extern __shared__ __align__(16) uint2 sgt[];
    uint2* thH2 = sgt;               // 16 * GQ
    uint2* thL2 = sgt + 16 * GQ;     // 16 * GQ

    int k  = blockIdx.x;
    int nt = blockIdx.y;
    int tid = threadIdx.x;
    int w = tid >> 5, lane = tid & 31;
    int g = lane >> 2, tg = lane & 3;
    int vbase = w * 16;

    const float* Tk = Theta + (size_t)k * FF * FOUT;
    for (int idx = tid; idx < 2048; idx += 416) {
        int f2 = idx >> 6, fo = idx & 63;
        float t0 = Tk[(2 * f2) * 64 + fo];
        float t1 = Tk[(2 * f2 + 1) * 64 + fo];
        u32 h = cvt_bf2(t0, t1);
        float h0 = __uint_as_float(h << 16);
        float h1 = __uint_as_float(h & 0xffff0000u);
        u32 l = cvt_bf2(t0 - h0, t1 - h1);
        int ks = f2 >> 3, tgx = f2 & 7;
        int q = 4 * ks + (tgx & 3);
        if (tgx < 4) { thH2[q * GQ + fo].x = h; thL2[q * GQ + fo].x = l; }
        else         { thH2[q * GQ + fo].y = h; thL2[q * GQ + fo].y = l; }
    }
    __syncthreads();

    const float* xnt = x + (size_t)nt * VV * FF;
    int r0 = vbase + g;
    int r1 = r0 + 8;
    bool ok1 = (r1 < VV);
    float2 xr[4][4];
#pragma unroll
    for (int ks = 0; ks < 4; ++ks) {
        int f = 16 * ks + 2 * tg;
        xr[ks][0] = *(const float2*)(xnt + (size_t)r0 * FF + f);
        xr[ks][2] = *(const float2*)(xnt + (size_t)r0 * FF + f + 8);
        if (ok1) {
            xr[ks][1] = *(const float2*)(xnt + (size_t)r1 * FF + f);
            xr[ks][3] = *(const float2*)(xnt + (size_t)r1 * FF + f + 8);
        } else {
            xr[ks][1] = make_float2(0.f, 0.f);
            xr[ks][3] = make_float2(0.f, 0.f);
        }
    }

    float acc[8][4];
#pragma unroll
    for (int nn = 0; nn < 8; ++nn)
#pragma unroll
        for (int j = 0; j < 4; ++j) acc[nn][j] = 0.f;

#pragma unroll
    for (int ks = 0; ks < 4; ++ks) {
        u32 Ah[4], Al[4];
#pragma unroll
        for (int s = 0; s < 4; ++s) {
            float a0 = xr[ks][s].x, a1 = xr[ks][s].y;
            u32 h = cvt_bf2(a0, a1);
            float h0 = __uint_as_float(h << 16);
            float h1 = __uint_as_float(h & 0xffff0000u);
            Ah[s] = h;
            Al[s] = cvt_bf2(a0 - h0, a1 - h1);
        }
        int fbq = (4 * ks + tg) * GQ;
#pragma unroll
        for (int nn = 0; nn < 8; ++nn) {
            int fo = 8 * nn + g;
            uint2 BhP = thH2[fbq + fo];
            uint2 BlP = thL2[fbq + fo];
            u32 Bh[2] = { BhP.x, BhP.y };
            u32 Bl[2] = { BlP.x, BlP.y };
            mma16(acc[nn], Ah, Bh);
            mma16(acc[nn], Ah, Bl);
            mma16(acc[nn], Al, Bh);
        }
    }

    float* yk = (k == 0 ? g_y0 : (k == 1 ? g_y1 : g_y2)) + (size_t)nt * VV * FOUT;
#pragma unroll
    for (int nn = 0; nn < 8; ++nn) {
        int c = 8 * nn + 2 * tg;
        *(float2*)(yk + (size_t)r0 * FOUT + c) = make_float2(acc[nn][0], acc[nn][1]);
        if (ok1)
            *(float2*)(yk + (size_t)r1 * FOUT + c) = make_float2(acc[nn][2], acc[nn][3]);
    }

    if (k != 0) {
        u32* ypk = (k == 1 ? g_y1p : g_y2p) + (size_t)nt * 100 * FOUT;
#pragma unroll
        for (int nn = 0; nn < 8; ++nn) {
            float s0 = __shfl_down_sync(0xffffffffu, acc[nn][0], 4);
            float s1 = __shfl_down_sync(0xffffffffu, acc[nn][1], 4);
            float s2 = __shfl_down_sync(0xffffffffu, acc[nn][2], 4);
            float s3 = __shfl_down_sync(0xffffffffu, acc[nn][3], 4);
            if (!(g & 1)) {
                int c = 8 * nn + 2 * tg;
                int u2a = r0 >> 1;
                *(uint2*)(ypk + (size_t)u2a * FOUT + c) =
                    make_uint2(cvt_bf2(acc[nn][0], s0), cvt_bf2(acc[nn][1], s1));
                if (ok1)
                    *(uint2*)(ypk + (size_t)(u2a + 4) * FOUT + c) =
                        make_uint2(cvt_bf2(acc[nn][2], s2), cvt_bf2(acc[nn][3], s3));
            }
        }
    }
}

// ---------------------------------------------------------------------------
// kernelBtc v5: grid (2, NT) — CTA h owns v in [112h, 112h+112); 224 thr.
//   Triple-buffered smem (S rows / S cols / yp), depth-2 cp.async prefetch,
//   ONE __syncthreads per chunk. Division-free staging (literal divisors).
//   Att via direct LDG (L2-hot).
// ---------------------------------------------------------------------------
#define SRS 116                 // s_row stride (floats), per-half
#define SCT 20                  // s_col row stride (floats)
#define SYP 72                  // yp row stride (u32)
#define BUF_SR (KC * SRS)       // 1856
#define BUF_SC (112 * SCT)      // 2240
#define BUF_YP (8 * SYP)        // 576 (u32)
#define OFF_SR 0                             // [3] x 1856
#define OFF_SC (3 * BUF_SR)                  // 5568, [3] x 2240
#define OFF_YP1 (OFF_SC + 3 * BUF_SC)        // 12288, [3] x 576
#define OFF_YP2 (OFF_YP1 + 3 * BUF_YP)       // 14016, [3] x 576
#define SMB_WORDS (OFF_YP2 + 3 * BUF_YP)     // 15744 words = 62976 B

__global__ void __launch_bounds__(224, 3) kernelBtc(const float* __restrict__ S,
                                                    const float* __restrict__ Att,
                                                    float* __restrict__ out) {
    extern __shared__ __align__(16) float sm[];
    int h  = blockIdx.x;                  // v half
    int nt = blockIdx.y;
    int n  = nt / TT;
    int tid = threadIdx.x;
    int w = tid >> 5, lane = tid & 31;
    int g = lane >> 2, tg = lane & 3;
    int voff = 112 * h;
    int vbase = voff + w * 16;
    bool active = (vbase < VV);

    const int ncol16 = h ? 22 : 28;       // valid 16B col-chunks (predicate only)
    const int nvr    = h ? 88 : 112;      // valid S-col rows (predicate only)

    const float* Snt = S + (size_t)nt * VV * VV;
    const float* Atn = Att + (size_t)n * VV * VV;
    const float* y0g = g_y0 + (size_t)nt * VV * FOUT;
    const float* y1g = g_y1 + (size_t)nt * VV * FOUT;
    const float* y2g = g_y2 + (size_t)nt * VV * FOUT;
    const u32* y1pg = g_y1p + (size_t)nt * 100 * FOUT;
    const u32* y2pg = g_y2p + (size_t)nt * 100 * FOUT;

    float acc[8][4];
#pragma unroll
    for (int nn = 0; nn < 8; ++nn)
#pragma unroll
        for (int j = 0; j < 4; ++j) acc[nn][j] = 0.f;
    float dacc[2] = {0.f, 0.f};

    // ---- staging: all divisions by literals / shifts ----
    auto stage_full = [&](int c, int b) {
        int u0 = c * KC;
        float* srb = sm + OFF_SR + b * BUF_SR;
        float* scb = sm + OFF_SC + b * BUF_SC;
        // S rows: 16 x 28 slots = 448 = 2 iterations
#pragma unroll
        for (int it = 0; it < 2; ++it) {
            int i = tid + it * 224;
            int r = i / 28, s = i - r * 28;          // literal 28
            if (s < ncol16)
                cpa16((u32)__cvta_generic_to_shared(srb + r * SRS + s * 4),
                      Snt + (size_t)(u0 + r) * VV + voff + s * 4);
        }
        // S cols: 112 x 4 slots = 448 = 2 iterations
#pragma unroll
        for (int it = 0; it < 2; ++it) {
            int i = tid + it * 224;
            int r = i >> 2, s = i & 3;
            if (r < nvr)
                cpa16((u32)__cvta_generic_to_shared(scb + r * SCT + s * 4),
                      Snt + (size_t)(voff + r) * VV + u0 + s * 4);
        }
        // yp: 8 rows x 16 slots = 128
        if (tid < 128) {
            int r = tid >> 4, s = tid & 15;
            cpa16((u32)__cvta_generic_to_shared((u32*)sm + OFF_YP1 + b * BUF_YP + r * SYP + s * 4),
                  y1pg + (size_t)(8 * c + r) * FOUT + s * 4);
            cpa16((u32)__cvta_generic_to_shared((u32*)sm + OFF_YP2 + b * BUF_YP + r * SYP + s * 4),
                  y2pg + (size_t)(8 * c + r) * FOUT + s * 4);
        }
        CP_COMMIT();
    };
    auto stage_last = [&](int b) {       // c = NCH-1, uw = 8, u0 = 192
        const int u0 = (NCH - 1) * KC;
        float* srb = sm + OFF_SR + b * BUF_SR;
        float* scb = sm + OFF_SC + b * BUF_SC;
        // S rows: 8 x 28 = 224 = 1 iteration
        {
            int r = tid / 28, s = tid - r * 28;
            if (s < ncol16)
                cpa16((u32)__cvta_generic_to_shared(srb + r * SRS + s * 4),
                      Snt + (size_t)(u0 + r) * VV + voff + s * 4);
        }
        // S cols: 112 x 2 = 224 = 1 iteration
        {
            int r = tid >> 1, s = tid & 1;
            if (r < nvr)
                cpa16((u32)__cvta_generic_to_shared(scb + r * SCT + s * 4),
                      Snt + (size_t)(voff + r) * VV + u0 + s * 4);
        }
        // yp: 4 rows x 16 = 64
        if (tid < 64) {
            int r = tid >> 4, s = tid & 15;
            cpa16((u32)__cvta_generic_to_shared((u32*)sm + OFF_YP1 + b * BUF_YP + r * SYP + s * 4),
                  y1pg + (size_t)(8 * (NCH - 1) + r) * FOUT + s * 4);
            cpa16((u32)__cvta_generic_to_shared((u32*)sm + OFF_YP2 + b * BUF_YP + r * SYP + s * 4),
                  y2pg + (size_t)(8 * (NCH - 1) + r) * FOUT + s * 4);
        }
        CP_COMMIT();
    };

    stage_full(0, 0);
    stage_full(1, 1);

    int uA = 2 * tg, uC = 2 * tg + 8;
    int vloc = 16 * w + g;               // local v row in this half
    int vA = voff + vloc, vB = vA + 8;
    bool vtail = (vbase + 15 >= VV);

    int bc = 0, bst = 2;
    for (int c = 0; c < NCH; ++c) {
        int u0 = c * KC;
        if (c == NCH - 1) { CP_WAIT_ALL(); } else { CP_WAIT_1(); }
        __syncthreads();                 // ONE barrier per chunk

        if (active) {
            const float* sr = sm + OFF_SR + bc * BUF_SR;
            const float* sc = sm + OFF_SC + bc * BUF_SC;

            // ---- A fragments ----
            u32 af1[4], af2[4];
            {
                float c1v[2][4], c2v[2][4];
                bool fast = (u0 != vbase) && (c != NCH - 1) && !vtail;
                if (fast) {
#pragma unroll
                    for (int s = 0; s < 4; ++s) {
                        int ul = (s < 2) ? (uA + s) : (uC + s - 2);
                        int ugl = u0 + ul;
                        float mA = fminf(sr[ul * SRS + vloc], sc[vloc * SCT + ul]);
                        float mB = fminf(sr[ul * SRS + vloc + 8], sc[(vloc + 8) * SCT + ul]);
                        float aA = Atn[(size_t)ugl * VV + vA];
                        float aB = Atn[(size_t)ugl * VV + vB];
                        dacc[0] += mA; dacc[1] += mB;
                        float p1A = -mA * aA, p1B = -mB * aB;
                        c1v[0][s] = p1A;  c2v[0][s] = -2.f * mA * p1A;
                        c1v[1][s] = p1B;  c2v[1][s] = -2.f * mB * p1B;
                    }
                } else {
#pragma unroll
                    for (int s = 0; s < 4; ++s) {
                        int ul = (s < 2) ? (uA + s) : (uC + s - 2);
                        int ugl = u0 + ul;
                        bool uok = (ugl < VV);
                        bool rB  = (vB < VV);
                        float mA = fminf(sr[ul * SRS + vloc], sc[vloc * SCT + ul]);
                        float mB = fminf(sr[ul * SRS + vloc + 8], sc[(vloc + 8) * SCT + ul]);
                        float aA = uok ? Atn[(size_t)ugl * VV + vA] : 0.f;
                        float aB = (uok && rB) ? Atn[(size_t)ugl * VV + vB] : 0.f;
                        if (uok) { dacc[0] += mA; dacc[1] += mB; }
                        bool okA = uok && (ugl != vA);
                        bool okB = uok && rB && (ugl != vB);
                        float p1A = -mA * aA, p1B = -mB * aB;
                        c1v[0][s] = okA ? p1A : 0.f;  c2v[0][s] = okA ? -2.f * mA * p1A : 0.f;
                        c1v[1][s] = okB ? p1B : 0.f;  c2v[1][s] = okB ? -2.f * mB * p1B : 0.f;
                    }
                }
                af1[0] = cvt_bf2(c1v[0][0], c1v[0][1]);
                af1[1] = cvt_bf2(c1v[1][0], c1v[1][1]);
                af1[2] = cvt_bf2(c1v[0][2], c1v[0][3]);
                af1[3] = cvt_bf2(c1v[1][2], c1v[1][3]);
                af2[0] = cvt_bf2(c2v[0][0], c2v[0][1]);
                af2[1] = cvt_bf2(c2v[1][0], c2v[1][1]);
                af2[2] = cvt_bf2(c2v[0][2], c2v[0][3]);
                af2[3] = cvt_bf2(c2v[1][2], c2v[1][3]);
            }

            // ---- prefetch chunk c+2 (writes buf bst = (c+2)%3, safe: last
            //      read in chunk c-1, fenced by this chunk's barrier) ----
            if (c + 2 < NCH) {
                if (c + 2 == NCH - 1) stage_last(bst); else stage_full(c + 2, bst);
            }

            // ---- MMA phase: pre-packed B-frags from yp[bc] ----
            const u32* sy1 = (const u32*)sm + OFF_YP1 + bc * BUF_YP;
            const u32* sy2 = (const u32*)sm + OFF_YP2 + bc * BUF_YP;
#pragma unroll
            for (int nn = 0; nn < 8; ++nn) {
                int fo = 8 * nn + g;
                u32 b1[2] = { sy1[tg * SYP + fo], sy1[(tg + 4) * SYP + fo] };
                u32 b2[2] = { sy2[tg * SYP + fo], sy2[(tg + 4) * SYP + fo] };
                mma16(acc[nn], af1, b1);
                mma16(acc[nn], af2, b2);
            }
        } else {
            // inactive warp still participates in staging
            if (c + 2 < NCH) {
                if (c + 2 == NCH - 1) stage_last(bst); else stage_full(c + 2, bst);
            }
        }
        bc  = (bc  == 2) ? 0 : bc + 1;
        bst = (bst == 2) ? 0 : bst + 1;
    }

    if (!active) return;

    // ---- reduce d over tg lanes ----
    float dred[2];
#pragma unroll
    for (int hh = 0; hh < 2; ++hh) {
        float dv = dacc[hh];
        dv += __shfl_xor_sync(0xffffffffu, dv, 1);
        dv += __shfl_xor_sync(0xffffffffu, dv, 2);
        dred[hh] = dv;
    }

    // ---- epilogue: exact fp32 diagonal base + off-diag acc, relu ----
#pragma unroll
    for (int hh = 0; hh < 2; ++hh) {
        int v = vbase + g + 8 * hh;
        if (v < VV) {
            float avv = Atn[(size_t)v * VV + v];
            float svv = Snt[(size_t)v * VV + v];
            float l = dred[hh] - 1.0f - svv;
            float c1d = l * avv;
            float c2d = (2.0f * l * l - 1.0f) * avv;
            const float* y0r = y0g + (size_t)v * FOUT;
            const float* y1r = y1g + (size_t)v * FOUT;
            const float* y2r = y2g + (size_t)v * FOUT;
            float* orow = out + ((size_t)nt * VV + v) * FOUT;
#pragma unroll
            for (int nn = 0; nn < 8; ++nn) {
                int fo = 8 * nn + 2 * tg;
                float2 p0 = *(const float2*)(y0r + fo);
                float2 p1 = *(const float2*)(y1r + fo);
                float2 p2 = *(const float2*)(y2r + fo);
                float2 o;
                o.x = fmaxf(avv * p0.x + c1d * p1.x + c2d * p2.x
                            + acc[nn][2 * hh + 0], 0.f);
                o.y = fmaxf(avv * p0.y + c1d * p1.y + c2d * p2.y
                            + acc[nn][2 * hh + 1], 0.f);
                *(float2*)(orow + fo) = o;
            }
        }
    }
}

// ---------------------------------------------------------------------------
extern "C" void kernel_launch(void* const* d_in, const int* in_sizes, int n_in,
                              void* d_out, int out_size) {
    (void)in_sizes; (void)n_in; (void)out_size;
    const float* x     = (const float*)d_in[0];
    const float* Att   = (const float*)d_in[1];
    const float* S     = (const float*)d_in[2];
    const float* Theta = (const float*)d_in[3];
    float* out = (float*)d_out;

    const int smemG = 32 * GQ * 8;        // 19456
    const int smemB = SMB_WORDS * 4;      // 62976
    cudaFuncSetAttribute(kernelGtc, cudaFuncAttributeMaxDynamicSharedMemorySize, smemG);
    cudaFuncSetAttribute(kernelBtc, cudaFuncAttributeMaxDynamicSharedMemorySize, smemB);

    kernelGtc<<<dim3(3, NT), 416, smemG>>>(x, Theta);
    kernelBtc<<<dim3(2, NT), 224, smemB>>>(S, Att, out);
}

// round 17
// speedup vs baseline: 1.0846x; 1.0846x over previous
#include <cuda_runtime.h>
#include <cstdint>

#define NN 8
#define TT 64
#define VV 200
#define FF 64
#define FOUT 64
#define NT 512
#define KC 16          // u per chunk in contraction
#define NCH 13         // 12 full + 1 partial (8u)
#define THREADS 416
#define GQ 76          // uint2 row stride for packed Theta

typedef unsigned long long u64;
typedef unsigned int u32;

__device__ __forceinline__ void cpa16(u32 dst, const void* src) {
    asm volatile("cp.async.cg.shared.global [%0], [%1], 16;" :: "r"(dst), "l"(src));
}
#define CP_COMMIT()   asm volatile("cp.async.commit_group;" ::: "memory")
#define CP_WAIT_ALL() asm volatile("cp.async.wait_group 0;" ::: "memory")

__device__ __forceinline__ u32 cvt_bf2(float lo, float hi) {
    u32 r; asm("cvt.rn.bf16x2.f32 %0, %1, %2;" : "=r"(r) : "f"(hi), "f"(lo)); return r;
}
__device__ __forceinline__ void mma16(float* d, const u32* a, const u32* b) {
    asm volatile(
        "mma.sync.aligned.m16n8k16.row.col.f32.bf16.bf16.f32 "
        "{%0,%1,%2,%3},{%4,%5,%6,%7},{%8,%9},{%0,%1,%2,%3};"
        : "+f"(d[0]), "+f"(d[1]), "+f"(d[2]), "+f"(d[3])
        : "r"(a[0]), "r"(a[1]), "r"(a[2]), "r"(a[3]),
          "r"(b[0]), "r"(b[1]));
}

// ---- smem layout (32-bit words) ----
#define W_YP1 0                         // 104*72 u32 = 7488
#define W_YP2 7488                      // 7488
#define W_Y0  14976                     // 32*416 f32 = 13312
#define W_UN  28288                     // union: theta 14592 / S bufs 15296
#define SRS 228
#define SCT 20
#define BUF_SR (KC * SRS)               // 3648
#define BUF_SC (VV * SCT)               // 4000
#define SM_WORDS (W_UN + 2 * BUF_SR + 2 * BUF_SC)   // 43584 -> 174336 B

__global__ void __launch_bounds__(THREADS, 1) kernelFused(
        const float* __restrict__ x,
        const float* __restrict__ Att,
        const float* __restrict__ S,
        const float* __restrict__ Theta,
        float* __restrict__ out) {
    extern __shared__ __align__(16) float sm[];
    u32* yp1 = (u32*)sm + W_YP1;
    u32* yp2 = (u32*)sm + W_YP2;
    float* y0s = sm + W_Y0;
    uint2* thb = (uint2*)(sm + W_UN);

    int nt = blockIdx.x;
    int n  = nt / TT;
    int tid = threadIdx.x;
    int w = tid >> 5, lane = tid & 31;
    int g = lane >> 2, tg = lane & 3;
    int vbase = w * 16;

    const float* Snt = S + (size_t)nt * VV * VV;
    const float* Atn = Att + (size_t)n * VV * VV;

    // ================= phase 0: pack Theta (3 k) + zero yp pad rows =========
    for (int idx = tid; idx < 3 * 2048; idx += THREADS) {
        int kk = idx >> 11;
        int r  = idx & 2047;
        int f2 = r >> 6, fo = r & 63;
        const float* Tk = Theta + (size_t)kk * FF * FOUT;
        float t0 = Tk[(2 * f2) * 64 + fo];
        float t1 = Tk[(2 * f2 + 1) * 64 + fo];
        u32 hh = cvt_bf2(t0, t1);
        float h0 = __uint_as_float(hh << 16);
        float h1 = __uint_as_float(hh & 0xffff0000u);
        u32 ll = cvt_bf2(t0 - h0, t1 - h1);
        uint2* H = thb + kk * (2 * 16 * GQ);
        uint2* L = H + 16 * GQ;
        int ks = f2 >> 3, tgx = f2 & 7;
        int q = 4 * ks + (tgx & 3);
        if (tgx < 4) { H[q * GQ + fo].x = hh; L[q * GQ + fo].x = ll; }
        else         { H[q * GQ + fo].y = hh; L[q * GQ + fo].y = ll; }
    }
    if (tid < 288) {            // zero yp rows 100..103 (B-frag tail reads)
        yp1[100 * 72 + tid] = 0u;
        yp2[100 * 72 + tid] = 0u;
    }
    __syncthreads();

    // ================= phase 1: y_k = x @ Theta_k (warp owns its 16 rows) ===
    const float* xnt = x + (size_t)nt * VV * FF;
    int r0 = vbase + g;
    int r1 = r0 + 8;
    bool ok1 = (r1 < VV);
    float2 xr[4][4];
#pragma unroll
    for (int ks = 0; ks < 4; ++ks) {
        int f = 16 * ks + 2 * tg;
        xr[ks][0] = *(const float2*)(xnt + (size_t)r0 * FF + f);
        xr[ks][2] = *(const float2*)(xnt + (size_t)r0 * FF + f + 8);
        if (ok1) {
            xr[ks][1] = *(const float2*)(xnt + (size_t)r1 * FF + f);
            xr[ks][3] = *(const float2*)(xnt + (size_t)r1 * FF + f + 8);
        } else {
            xr[ks][1] = make_float2(0.f, 0.f);
            xr[ks][3] = make_float2(0.f, 0.f);
        }
    }

    auto gemm_k = [&](float (&a)[8][4], int kk) {
        const uint2* H = thb + kk * (2 * 16 * GQ);
        const uint2* L = H + 16 * GQ;
#pragma unroll
        for (int ks = 0; ks < 4; ++ks) {
            u32 Ah[4], Al[4];
#pragma unroll
            for (int s = 0; s < 4; ++s) {
                float a0 = xr[ks][s].x, a1 = xr[ks][s].y;
                u32 hh = cvt_bf2(a0, a1);
                float h0 = __uint_as_float(hh << 16);
                float h1 = __uint_as_float(hh & 0xffff0000u);
                Ah[s] = hh;
                Al[s] = cvt_bf2(a0 - h0, a1 - h1);
            }
            int fbq = (4 * ks + tg) * GQ;
#pragma unroll
            for (int nn = 0; nn < 8; ++nn) {
                int fo = 8 * nn + g;
                uint2 BhP = H[fbq + fo];
                uint2 BlP = L[fbq + fo];
                u32 Bh[2] = { BhP.x, BhP.y };
                u32 Bl[2] = { BlP.x, BlP.y };
                mma16(a[nn], Ah, Bh);
                mma16(a[nn], Ah, Bl);
                mma16(a[nn], Al, Bh);
            }
        }
    };
    auto store_yp = [&](float (&a)[8][4], u32* yp) {
#pragma unroll
        for (int nn = 0; nn < 8; ++nn) {
            float s0 = __shfl_down_sync(0xffffffffu, a[nn][0], 4);
            float s1 = __shfl_down_sync(0xffffffffu, a[nn][1], 4);
            float s2 = __shfl_down_sync(0xffffffffu, a[nn][2], 4);
            float s3 = __shfl_down_sync(0xffffffffu, a[nn][3], 4);
            if (!(g & 1)) {
                int c = 8 * nn + 2 * tg;
                int u2a = r0 >> 1;
                *(uint2*)(yp + u2a * 72 + c) =
                    make_uint2(cvt_bf2(a[nn][0], s0), cvt_bf2(a[nn][1], s1));
                if (ok1)
                    *(uint2*)(yp + (u2a + 4) * 72 + c) =
                        make_uint2(cvt_bf2(a[nn][2], s2), cvt_bf2(a[nn][3], s3));
            }
        }
    };

    {
        float yt[8][4];
#pragma unroll
        for (int nn = 0; nn < 8; ++nn)
#pragma unroll
            for (int j = 0; j < 4; ++j) yt[nn][j] = 0.f;
        gemm_k(yt, 0);
#pragma unroll
        for (int nn = 0; nn < 8; ++nn)
#pragma unroll
            for (int j = 0; j < 4; ++j)
                y0s[(nn * 4 + j) * THREADS + tid] = yt[nn][j];
    }
    float y1a[8][4], y2a[8][4];
#pragma unroll
    for (int nn = 0; nn < 8; ++nn)
#pragma unroll
        for (int j = 0; j < 4; ++j) { y1a[nn][j] = 0.f; y2a[nn][j] = 0.f; }
    gemm_k(y1a, 1);
    store_yp(y1a, yp1);
    gemm_k(y2a, 2);
    store_yp(y2a, yp2);
    __syncthreads();           // yp complete; theta region now free for S bufs

    // ================= phase 2: contraction over u, fused msym/d ============
    float* sr0 = sm + W_UN;                    // [2] x BUF_SR
    float* sc0 = sm + W_UN + 2 * BUF_SR;       // [2] x BUF_SC

    auto stage = [&](int c) {
        int u0 = c * KC;
        int b = c & 1;
        float* srb = sr0 + b * BUF_SR;
        float* scb = sc0 + b * BUF_SC;
        if (c != NCH - 1) {
#pragma unroll
            for (int it = 0; it < 2; ++it) {
                int i = tid + it * THREADS;
                if (i < 800) {
                    int r = i / 50, s = i - r * 50;
                    cpa16((u32)__cvta_generic_to_shared(srb + r * SRS + s * 4),
                          Snt + (size_t)(u0 + r) * VV + s * 4);
                }
            }
#pragma unroll
            for (int it = 0; it < 2; ++it) {
                int i = tid + it * THREADS;
                if (i < 800) {
                    int r = i >> 2, s = i & 3;
                    cpa16((u32)__cvta_generic_to_shared(scb + r * SCT + s * 4),
                          Snt + (size_t)r * VV + u0 + s * 4);
                }
            }
        } else {
            if (tid < 400) {
                int r = tid / 50, s = tid - r * 50;
                cpa16((u32)__cvta_generic_to_shared(srb + r * SRS + s * 4),
                      Snt + (size_t)(u0 + r) * VV + s * 4);
            }
            if (tid < 400) {
                int r = tid >> 1, s = tid & 1;
                cpa16((u32)__cvta_generic_to_shared(scb + r * SCT + s * 4),
                      Snt + (size_t)r * VV + u0 + s * 4);
            }
        }
        CP_COMMIT();
    };

    stage(0);

    float acc[8][4];
#pragma unroll
    for (int nn = 0; nn < 8; ++nn)
#pragma unroll
        for (int j = 0; j < 4; ++j) acc[nn][j] = 0.f;
    float dacc[2] = {0.f, 0.f};

    int uA = 2 * tg, uC = 2 * tg + 8;
    int vA = vbase + g;
    int vB = vA + 8;
    bool vtail = (w == 12);
    int vBs = (vB < VV) ? vB : vA;       // CLAMPED index for SHARED reads
                                          // (value discarded when vB OOB)

    for (int c = 0; c < NCH; ++c) {
        int b = c & 1;
        int u0 = c * KC;
        CP_WAIT_ALL();
        __syncthreads();
        if (c + 1 < NCH) stage(c + 1);   // buf b^1: last read in chunk c-1

        const float* sr = sr0 + b * BUF_SR;
        const float* sc = sc0 + b * BUF_SC;

        // ---- A fragments ----
        u32 af1[4], af2[4];
        {
            float c1v[2][4], c2v[2][4];
            bool fast = (c != w) && (c != NCH - 1) && !vtail;
            if (fast) {
#pragma unroll
                for (int s = 0; s < 4; ++s) {
                    int ul = (s < 2) ? (uA + s) : (uC + s - 2);
                    int ugl = u0 + ul;
                    float mA = fminf(sr[ul * SRS + vA], sc[vA * SCT + ul]);
                    float mB = fminf(sr[ul * SRS + vB], sc[vB * SCT + ul]);
                    float aA = Atn[(size_t)ugl * VV + vA];
                    float aB = Atn[(size_t)ugl * VV + vB];
                    dacc[0] += mA; dacc[1] += mB;
                    float p1A = -mA * aA, p1B = -mB * aB;
                    c1v[0][s] = p1A;  c2v[0][s] = -2.f * mA * p1A;
                    c1v[1][s] = p1B;  c2v[1][s] = -2.f * mB * p1B;
                }
            } else {
#pragma unroll
                for (int s = 0; s < 4; ++s) {
                    int ul = (s < 2) ? (uA + s) : (uC + s - 2);
                    int ugl = u0 + ul;
                    bool uok = (ugl < VV);
                    bool rB  = (vB < VV);
                    float mA = fminf(sr[ul * SRS + vA], sc[vA * SCT + ul]);
                    float mB = fminf(sr[ul * SRS + vBs], sc[vBs * SCT + ul]);
                    float aA = uok ? Atn[(size_t)ugl * VV + vA] : 0.f;
                    float aB = (uok && rB) ? Atn[(size_t)ugl * VV + vB] : 0.f;
                    if (uok) { dacc[0] += mA; dacc[1] += mB; }
                    bool okA = uok && (ugl != vA);
                    bool okB = uok && rB && (ugl != vB);
                    float p1A = -mA * aA, p1B = -mB * aB;
                    c1v[0][s] = okA ? p1A : 0.f;  c2v[0][s] = okA ? -2.f * mA * p1A : 0.f;
                    c1v[1][s] = okB ? p1B : 0.f;  c2v[1][s] = okB ? -2.f * mB * p1B : 0.f;
                }
            }
            af1[0] = cvt_bf2(c1v[0][0], c1v[0][1]);
            af1[1] = cvt_bf2(c1v[1][0], c1v[1][1]);
            af1[2] = cvt_bf2(c1v[0][2], c1v[0][3]);
            af1[3] = cvt_bf2(c1v[1][2], c1v[1][3]);
            af2[0] = cvt_bf2(c2v[0][0], c2v[0][1]);
            af2[1] = cvt_bf2(c2v[1][0], c2v[1][1]);
            af2[2] = cvt_bf2(c2v[0][2], c2v[0][3]);
            af2[3] = cvt_bf2(c2v[1][2], c2v[1][3]);
        }

        // ---- MMA phase: B-frags straight from resident yp smem ----
#pragma unroll
        for (int nn = 0; nn < 8; ++nn) {
            int fo = 8 * nn + g;
            u32 b1[2] = { yp1[(tg + 8 * c) * 72 + fo], yp1[(tg + 4 + 8 * c) * 72 + fo] };
            u32 b2[2] = { yp2[(tg + 8 * c) * 72 + fo], yp2[(tg + 4 + 8 * c) * 72 + fo] };
            mma16(acc[nn], af1, b1);
            mma16(acc[nn], af2, b2);
        }
    }

    // ---- reduce d over tg lanes ----
    float dred[2];
#pragma unroll
    for (int hh = 0; hh < 2; ++hh) {
        float dv = dacc[hh];
        dv += __shfl_xor_sync(0xffffffffu, dv, 1);
        dv += __shfl_xor_sync(0xffffffffu, dv, 2);
        dred[hh] = dv;
    }

    // ---- epilogue: exact fp32 diagonal (y from regs/smem) + off-diag, relu -
#pragma unroll
    for (int hh = 0; hh < 2; ++hh) {
        int v = vbase + g + 8 * hh;
        if (v < VV) {
            float avv = Atn[(size_t)v * VV + v];
            float svv = Snt[(size_t)v * VV + v];
            float l = dred[hh] - 1.0f - svv;
            float c1d = l * avv;
            float c2d = (2.0f * l * l - 1.0f) * avv;
            float* orow = out + ((size_t)nt * VV + v) * FOUT;
#pragma unroll
            for (int nn = 0; nn < 8; ++nn) {
                int fo = 8 * nn + 2 * tg;
                float y00 = y0s[(nn * 4 + 2 * hh + 0) * THREADS + tid];
                float y01 = y0s[(nn * 4 + 2 * hh + 1) * THREADS + tid];
                float2 o;
                o.x = fmaxf(avv * y00 + c1d * y1a[nn][2 * hh + 0]
                            + c2d * y2a[nn][2 * hh + 0] + acc[nn][2 * hh + 0], 0.f);
                o.y = fmaxf(avv * y01 + c1d * y1a[nn][2 * hh + 1]
                            + c2d * y2a[nn][2 * hh + 1] + acc[nn][2 * hh + 1], 0.f);
                *(float2*)(orow + fo) = o;
            }
        }
    }
}

// ---------------------------------------------------------------------------
extern "C" void kernel_launch(void* const* d_in, const int* in_sizes, int n_in,
                              void* d_out, int out_size) {
    (void)in_sizes; (void)n_in; (void)out_size;
    const float* x     = (const float*)d_in[0];
    const float* Att   = (const float*)d_in[1];
    const float* S     = (const float*)d_in[2];
    const float* Theta = (const float*)d_in[3];
    float* out = (float*)d_out;

    const int smemF = SM_WORDS * 4;     // 174336
    cudaFuncSetAttribute(kernelFused, cudaFuncAttributeMaxDynamicSharedMemorySize, smemF);
    kernelFused<<<NT, THREADS, smemF>>>(x, Att, S, Theta, out);
}